// round 15
// baseline (speedup 1.0000x reference)
#include <cuda_runtime.h>
#include <cuda_fp16.h>
#include <stdint.h>

// Problem constants (fixed by dataset)
#define NL    4
#define Bz    64
#define Hd    512
#define Tmax  256
#define NCTA  128
#define NTHR  288     // 8 compute warps + 1 sync warp
#define NCOMP 256

#define RSTRIDE 66                       // padded row stride for reduction buf
#define SMEM_W   (4*64*32*16)            // 131072 B: A-fragments, 4 layers x 64 ktiles
#define SMEM_RED (4*16*RSTRIDE*4)        // 16896 B
#define SMEM_GO  (SMEM_W + SMEM_RED)     // 4B go-flag (+pad)
#define SMEM_TOT (SMEM_GO + 16)

// ---------------- persistent device state (no allocation allowed) ----------------
// Activations packed in B-fragment order, single fp16, 8B/lane = {b0,b1}
// plane = [32 ktiles][8 ntiles][32 lanes][4 halves] = 32768 halves
__device__ __align__(16) __half g_Xin [2][NL][32768];  // input to layer l, parity p
__device__ __align__(16) __half g_Hrec[2][NL][32768];  // recurrent h of layer l, parity p
__device__ unsigned g_bar;                             // monotonic; self-reset at end

// fast-math activations (MUFU-based, ~1e-6 rel err)
__device__ __forceinline__ float sigm(float x) {
    return __fdividef(1.0f, 1.0f + __expf(-x));
}
__device__ __forceinline__ float tanhfast(float x) {
    return __fdividef(2.0f, 1.0f + __expf(-2.0f * x)) - 1.0f;
}

// release-ordered arrive: orders all prior stores (collected by __syncthreads)
// before the counter increment becomes visible.
__device__ __forceinline__ void arrive_release(unsigned* bar) {
    asm volatile("red.release.gpu.global.add.u32 [%0], 1;" :: "l"(bar) : "memory");
}

// throttled spin on the global counter (sync warp only)
__device__ __forceinline__ void wait_ge(volatile unsigned* vb, unsigned target) {
    int spins = 0;
    while (*vb < target) {
        if (++spins > 4) __nanosleep(32);
    }
}

// offset of X element (k,n) inside a packed plane (single fp16)
__device__ __forceinline__ int xoff(int k, int n) {
    int kt = k >> 4, kr = k & 15, nt = n >> 3, nc = n & 7;
    int lane = nc * 4 + ((kr >> 1) & 3);
    return ((kt * 8 + nt) * 32 + lane) * 4 + ((kr >> 3) * 2 + (kr & 1));
}

__device__ __forceinline__ void mma16816(float* c,
                                         unsigned a0, unsigned a1, unsigned a2, unsigned a3,
                                         unsigned b0, unsigned b1) {
    asm volatile(
        "mma.sync.aligned.m16n8k16.row.col.f32.f16.f16.f32 "
        "{%0,%1,%2,%3}, {%4,%5,%6,%7}, {%8,%9}, {%0,%1,%2,%3};\n"
        : "+f"(c[0]), "+f"(c[1]), "+f"(c[2]), "+f"(c[3])
        : "r"(a0), "r"(a1), "r"(a2), "r"(a3), "r"(b0), "r"(b1));
}

// load 8 ktiles x 4 ntiles of B fragments (32 LDG.64, max MLP)
__device__ __forceinline__ void load_frags(uint2 bb[8][4], const uint2* __restrict__ Bp,
                                           int kt0, int nt0, int lane) {
#pragma unroll
    for (int q = 0; q < 8; q++)
#pragma unroll
        for (int n = 0; n < 4; n++)
            bb[q][n] = __ldcg(Bp + (((kt0 + q) * 8 + nt0 + n) * 32 + lane));
}

// preload 8 A-fragments (smem -> registers)
__device__ __forceinline__ void load_afrags(uint4 a[8], const uint4* __restrict__ sA) {
#pragma unroll
    for (int q = 0; q < 8; q++) a[q] = sA[q * 32];
}

// 32 MMAs from preloaded register A-fragments
__device__ __forceinline__ void mma_frags_reg(float acc[4][4], const uint4 a[8],
                                              uint2 bb[8][4]) {
#pragma unroll
    for (int q = 0; q < 8; q++)
#pragma unroll
        for (int n = 0; n < 4; n++)
            mma16816(acc[n], a[q].x, a[q].y, a[q].z, a[q].w, bb[q][n].x, bb[q][n].y);
}

// 32 MMAs reading A-fragments from smem (off-critical-path half)
__device__ __forceinline__ void mma_frags(float acc[4][4], const uint4* __restrict__ sA,
                                          uint2 bb[8][4]) {
#pragma unroll
    for (int q = 0; q < 8; q++) {
        uint4 a = sA[q * 32];
#pragma unroll
        for (int n = 0; n < 4; n++)
            mma16816(acc[n], a.x, a.y, a.z, a.w, bb[q][n].x, bb[q][n].y);
    }
}

// ---------------- single persistent kernel ----------------
// 8 compute warps: CTA owns 16 gate rows (4 units x 4 gates); warp w: kquad =
// w&3 (8 ktiles per half), nhalf = w>>2 (4 ntiles). Warp 8 = sync warp: it
// arrives, polls the global counter WHILE compute warps run shadow Hrec MMAs,
// and releases them via an smem go-flag (no post-wait __syncthreads).
__global__ void __launch_bounds__(NTHR, 1) lstm_all(
    const float* __restrict__ y,
    const float* __restrict__ h0,
    const float* __restrict__ c0,
    const float* __restrict__ Wih,
    const float* __restrict__ Whh,
    const float* __restrict__ bih,
    const float* __restrict__ bhh,
    const int*   __restrict__ seqp,
    float*       __restrict__ out)
{
    extern __shared__ char sm[];
    __half* sW  = (__half*)sm;            // [4][64][32] uint4 A-fragments
    float*  red = (float*)(sm + SMEM_W);  // [4 kquads][16 rows][RSTRIDE]
    int*    sgo = (int*)(sm + SMEM_GO);   // round go-flag

    const int tid  = threadIdx.x;
    const int cta  = blockIdx.x;
    const int w    = tid >> 5;
    const int lane = tid & 31;
    const int u0   = cta * 4;
    const unsigned sgo_addr = (unsigned)__cvta_generic_to_shared(sgo);

    if (tid == 0) *sgo = 0;

    // ---- prologue A: pack this CTA's weights straight into smem (fp16 frags) ----
    for (int idx = tid; idx < 8192; idx += NTHR) {   // idx = ((l*64+kt)*32+ln)
        int ln = idx & 31, kt = (idx >> 5) & 63, l = idx >> 11;
        const float* W = ((kt < 32) ? Wih : Whh) + (size_t)l * 4 * Hd * Hd;
        int kb = (kt & 31) * 16 + (ln & 3) * 2;
        __half h8[8];
#pragma unroll
        for (int areg = 0; areg < 4; areg++) {
            int r = (ln >> 2) + (areg & 1) * 8;   // A row 0..15
            int grow = (r & 3) * Hd + u0 + (r >> 2);
            float2 v = *(const float2*)&W[(size_t)grow * Hd + kb + (areg >> 1) * 8];
            h8[areg * 2 + 0] = __float2half_rn(v.x);
            h8[areg * 2 + 1] = __float2half_rn(v.y);
        }
        *(uint4*)&sW[(size_t)idx * 8] = *(uint4*)h8;
    }

    // ---- prologue B: pack initial state (grid-strided) ----
    for (int i = cta * NTHR + tid; i < (NL + 1) * Hd * Bz; i += NCTA * NTHR) {
        int u = (i & 32767) >> 6, b = i & 63;
        if (i < Hd * Bz)
            g_Xin[0][0][xoff(u, b)] = __float2half_rn(y[b * Hd + u]);
        else {
            int l = (i >> 15) - 1;
            g_Hrec[0][l][xoff(u, b)] =
                __float2half_rn(h0[(size_t)l * Bz * Hd + b * Hd + u]);
        }
    }

    // epilogue mapping: compute thread -> (unit j, batch c)
    const int j = (tid >> 6) & 3;
    const int c = tid & 63;
    const int u = u0 + j;
    const int xo = xoff(u, c);

    float cst[NL];
    float bias[NL][4];
    if (w < 8) {
#pragma unroll
        for (int l = 0; l < NL; l++)
            cst[l] = c0[(size_t)l * Bz * Hd + c * Hd + u];
#pragma unroll
        for (int l = 0; l < NL; l++)
#pragma unroll
            for (int g = 0; g < 4; g++)
                bias[l][g] = bih[l * 4 * Hd + g * Hd + u] + bhh[l * 4 * Hd + g * Hd + u];
    }

    int T = Tmax;
    if (seqp) { int tv = *seqp; if (tv > 0 && tv <= Tmax) T = tv; }
    const int R = NL * T;

    // ---- prologue grid barrier ----
    __syncthreads();
    if (tid == 0) {
        arrive_release(&g_bar);
        wait_ge(&g_bar, NCTA);
    }
    __syncthreads();

    // warp roles (compute warps)
    const int kq  = w & 3;          // K quadrant (8 ktiles per half)
    const int nt0 = ((w >> 2) & 1) * 4;  // first ntile of this warp's N half
    const int kt0 = kq * 8;         // plane-local first ktile
    const uint4* sA0 = (const uint4*)sW;

    uint2 bb[8][4];
    uint4 aX[8];
    float acc[4][4];

    if (w < 8) {
#pragma unroll
        for (int n = 0; n < 4; n++)
#pragma unroll
            for (int q = 0; q < 4; q++) acc[n][q] = 0.f;
        // Hrec half for round 0 (t=0, l=0, p=0)
        load_frags(bb, (const uint2*)&g_Hrec[0][0][0], kt0, nt0, lane);
        mma_frags(acc, sA0 + (0 * 64 + 32 + kt0) * 32 + lane, bb);
        // preload Xin A-frags for round 0
        load_afrags(aX, sA0 + (0 * 64 + kt0) * 32 + lane);
    }

    for (int r = 0; r < R; r++) {
        const int t = r >> 2, l = r & 3, p = t & 1;
        const int r2 = r + 1, l2 = r2 & 3, p2 = (r2 >> 2) & 1;

        if (w < 8) {
            // wait(r-1): spin on smem go-flag (set by sync warp); acquire
            if (r > 0) {
                unsigned v;
                do {
                    asm volatile("ld.acquire.cta.shared.u32 %0, [%1];"
                                 : "=r"(v) : "r"(sgo_addr));
                } while ((int)v < r);
            }

            // Xin half of round r (critical path; A-frags already in registers)
            load_frags(bb, (const uint2*)&g_Xin[p][l][0], kt0, nt0, lane);
            mma_frags_reg(acc, aX, bb);

            // cross-warp K reduction (4-way) via smem
            {
                int gid = lane >> 2, tig = lane & 3;
#pragma unroll
                for (int n = 0; n < 4; n++) {
                    int col = (nt0 + n) * 8 + tig * 2;
                    *(float2*)&red[(kq * 16 + gid)     * RSTRIDE + col] =
                        make_float2(acc[n][0], acc[n][1]);
                    *(float2*)&red[(kq * 16 + gid + 8) * RSTRIDE + col] =
                        make_float2(acc[n][2], acc[n][3]);
                }
            }
        }
        __syncthreads();   // S2: reduction tiles visible (sync warp passes through)

        float hn = 0.f;
        if (w < 8) {
            // early Hrec(r+1) fragment loads — latency hides under epilogue
            if (r2 < R)
                load_frags(bb, (const uint2*)&g_Hrec[p2][l2][0], kt0, nt0, lane);

            float s0 = 0.f, s1 = 0.f, s2 = 0.f, s3 = 0.f;
#pragma unroll
            for (int kk = 0; kk < 4; kk++) {
                const float* rw = &red[(kk * 16 + j * 4) * RSTRIDE + c];
                s0 += rw[0];
                s1 += rw[RSTRIDE];
                s2 += rw[2 * RSTRIDE];
                s3 += rw[3 * RSTRIDE];
            }

            float iG = sigm(s0 + bias[l][0]);
            float fG = sigm(s1 + bias[l][1]);
            float gG = tanhfast(s2 + bias[l][2]);
            float oG = sigm(s3 + bias[l][3]);
            float cn = fG * cst[l] + iG * gG;
            cst[l] = cn;
            hn = oG * tanhfast(cn);

            // critical-path publish: ONLY the next-round Xin destination
            unsigned short hb = __half_as_ushort(__float2half_rn(hn));
            __half* xdst = (l < NL - 1) ? &g_Xin[p][l + 1][0] : &g_Xin[p ^ 1][0][0];
            __stcg((unsigned short*)&xdst[xo], hb);
        }
        __syncthreads();   // S3: all Xin publishes collected

        if (w == 8) {
            // sync warp: arrive, observe, release compute warps via smem flag
            if (lane == 0) {
                arrive_release(&g_bar);
                if (r < R - 1) {
                    wait_ge(&g_bar, (unsigned)(r + 2) * NCTA);
                    asm volatile("fence.acq_rel.gpu;" ::: "memory");
                    asm volatile("st.release.cta.shared.u32 [%0], %1;"
                                 :: "r"(sgo_addr), "r"(r + 1) : "memory");
                }
            }
        } else {
            // shadow region: deferred publishes + Hrec MMAs for round r+1
            unsigned short hb = __half_as_ushort(__float2half_rn(hn));
            __stcg((unsigned short*)&g_Hrec[p ^ 1][l][xo], hb);
            if (l == NL - 1)
                out[((size_t)c * T + t) * Hd + u] = hn;   // out[b][t][u]

            if (r2 < R) {
#pragma unroll
                for (int n = 0; n < 4; n++)
#pragma unroll
                    for (int q = 0; q < 4; q++) acc[n][q] = 0.f;
                mma_frags(acc, sA0 + (l2 * 64 + 32 + kt0) * 32 + lane, bb);
                // preload Xin A-frags for round r+1 (before the flag spin)
                load_afrags(aX, sA0 + (l2 * 64 + kt0) * 32 + lane);
            }
        }
    }

    // self-reset barrier for next graph replay (deterministic state)
    if (cta == 0 && w == 8 && lane == 0) {
        wait_ge(&g_bar, (unsigned)(R + 1) * NCTA);
        *(volatile unsigned*)&g_bar = 0u;
    }
}

extern "C" void kernel_launch(void* const* d_in, const int* in_sizes, int n_in,
                              void* d_out, int out_size) {
    const float* y   = (const float*)d_in[0];
    const float* h0  = (const float*)d_in[1];
    const float* c0  = (const float*)d_in[2];
    const float* Wih = (const float*)d_in[3];
    const float* Whh = (const float*)d_in[4];
    const float* bih = (const float*)d_in[5];
    const float* bhh = (const float*)d_in[6];
    const int*   sl  = (n_in >= 8) ? (const int*)d_in[7] : nullptr;
    float* out = (float*)d_out;
    (void)in_sizes; (void)out_size;

    cudaFuncSetAttribute(lstm_all, cudaFuncAttributeMaxDynamicSharedMemorySize, SMEM_TOT);
    lstm_all<<<NCTA, NTHR, SMEM_TOT>>>(y, h0, c0, Wih, Whh, bih, bhh, sl, out);
}

// round 16
// speedup vs baseline: 1.2356x; 1.2356x over previous
#include <cuda_runtime.h>
#include <cuda_fp16.h>
#include <stdint.h>

// Problem constants (fixed by dataset)
#define NL    4
#define Bz    64
#define Hd    512
#define Tmax  256
#define NCTA  128
#define NTHR  256

#define RSTRIDE 66                       // padded row stride for reduction buf
#define SMEM_W   (4*64*32*16)            // 131072 B: A-fragments, 4 layers x 64 ktiles
#define SMEM_RED (4*16*RSTRIDE*4)        // 16896 B
#define SMEM_TOT (SMEM_W + SMEM_RED)

// ---------------- persistent device state (no allocation allowed) ----------------
// Activations packed in B-fragment order, single fp16, ntile-PAIRED so each
// lane's two adjacent-ntile fragments form one 16B unit (LDG.128):
// off(k,n) = ((kt*4 + nt/2)*32 + lane)*8 + (nt&1)*4 + frag
// plane = [32 kt][4 ntpair][32 lane][8 halves] = 32768 halves
__device__ __align__(16) __half g_Xin [2][NL][32768];  // input to layer l, parity p
__device__ __align__(16) __half g_Hrec[2][NL][32768];  // recurrent h of layer l, parity p
__device__ unsigned g_bar;                             // monotonic; self-reset at end

// fast-math activations (MUFU-based, ~1e-6 rel err)
__device__ __forceinline__ float sigm(float x) {
    return __fdividef(1.0f, 1.0f + __expf(-x));
}
__device__ __forceinline__ float tanhfast(float x) {
    return __fdividef(2.0f, 1.0f + __expf(-2.0f * x)) - 1.0f;
}

// release-ordered arrive: orders all prior stores (collected by __syncthreads)
// before the counter increment becomes visible.
__device__ __forceinline__ void arrive_release(unsigned* bar) {
    asm volatile("red.release.gpu.global.add.u32 [%0], 1;" :: "l"(bar) : "memory");
}

// throttled spin: a few hard polls, then back off
__device__ __forceinline__ void wait_ge(volatile unsigned* vb, unsigned target) {
    int spins = 0;
    while (*vb < target) {
        if (++spins > 4) __nanosleep(32);
    }
}

// offset of X element (k,n) inside a packed plane (paired-ntile layout)
__device__ __forceinline__ int xoff(int k, int n) {
    int kt = k >> 4, kr = k & 15, nt = n >> 3, nc = n & 7;
    int lane = nc * 4 + ((kr >> 1) & 3);
    int frag = (kr >> 3) * 2 + (kr & 1);
    return ((kt * 4 + (nt >> 1)) * 32 + lane) * 8 + (nt & 1) * 4 + frag;
}

__device__ __forceinline__ void mma16816(float* c,
                                         unsigned a0, unsigned a1, unsigned a2, unsigned a3,
                                         unsigned b0, unsigned b1) {
    asm volatile(
        "mma.sync.aligned.m16n8k16.row.col.f32.f16.f16.f32 "
        "{%0,%1,%2,%3}, {%4,%5,%6,%7}, {%8,%9}, {%0,%1,%2,%3};\n"
        : "+f"(c[0]), "+f"(c[1]), "+f"(c[2]), "+f"(c[3])
        : "r"(a0), "r"(a1), "r"(a2), "r"(a3), "r"(b0), "r"(b1));
}

// load 8 ktiles x 2 ntile-pairs of B fragments (16 LDG.128, max MLP)
__device__ __forceinline__ void load_frags(uint4 bb[8][2], const uint4* __restrict__ Bp,
                                           int kt0, int np0, int lane) {
#pragma unroll
    for (int q = 0; q < 8; q++)
#pragma unroll
        for (int np = 0; np < 2; np++)
            bb[q][np] = __ldcg(Bp + (((kt0 + q) * 4 + np0 + np) * 32 + lane));
}

// preload 8 A-fragments (smem -> registers)
__device__ __forceinline__ void load_afrags(uint4 a[8], const uint4* __restrict__ sA) {
#pragma unroll
    for (int q = 0; q < 8; q++) a[q] = sA[q * 32];
}

// 32 MMAs from preloaded register A-fragments
__device__ __forceinline__ void mma_frags_reg(float acc[4][4], const uint4 a[8],
                                              uint4 bb[8][2]) {
#pragma unroll
    for (int q = 0; q < 8; q++) {
        mma16816(acc[0], a[q].x, a[q].y, a[q].z, a[q].w, bb[q][0].x, bb[q][0].y);
        mma16816(acc[1], a[q].x, a[q].y, a[q].z, a[q].w, bb[q][0].z, bb[q][0].w);
        mma16816(acc[2], a[q].x, a[q].y, a[q].z, a[q].w, bb[q][1].x, bb[q][1].y);
        mma16816(acc[3], a[q].x, a[q].y, a[q].z, a[q].w, bb[q][1].z, bb[q][1].w);
    }
}

// 32 MMAs reading A-fragments from smem (off-critical-path half)
__device__ __forceinline__ void mma_frags(float acc[4][4], const uint4* __restrict__ sA,
                                          uint4 bb[8][2]) {
#pragma unroll
    for (int q = 0; q < 8; q++) {
        uint4 a = sA[q * 32];
        mma16816(acc[0], a.x, a.y, a.z, a.w, bb[q][0].x, bb[q][0].y);
        mma16816(acc[1], a.x, a.y, a.z, a.w, bb[q][0].z, bb[q][0].w);
        mma16816(acc[2], a.x, a.y, a.z, a.w, bb[q][1].x, bb[q][1].y);
        mma16816(acc[3], a.x, a.y, a.z, a.w, bb[q][1].z, bb[q][1].w);
    }
}

// ---------------- single persistent kernel (R14 structure) ----------------
// CTA owns 16 gate rows (4 units x 4 gates). Warp w: kquad = w&3 (8 ktiles per
// half), nhalf = w>>2 (ntile-pairs np0 = nhalf*2). Critical path carries ONLY
// the Xin publish; Hrec-plane and out stores deferred into the shadow region.
__global__ void __launch_bounds__(NTHR, 1) lstm_all(
    const float* __restrict__ y,
    const float* __restrict__ h0,
    const float* __restrict__ c0,
    const float* __restrict__ Wih,
    const float* __restrict__ Whh,
    const float* __restrict__ bih,
    const float* __restrict__ bhh,
    const int*   __restrict__ seqp,
    float*       __restrict__ out)
{
    extern __shared__ char sm[];
    __half* sW  = (__half*)sm;            // [4][64][32] uint4 A-fragments
    float*  red = (float*)(sm + SMEM_W);  // [4 kquads][16 rows][RSTRIDE]

    const int tid  = threadIdx.x;
    const int cta  = blockIdx.x;
    const int w    = tid >> 5;
    const int lane = tid & 31;
    const int u0   = cta * 4;

    // ---- prologue A: pack this CTA's weights straight into smem (fp16 frags) ----
#pragma unroll 4
    for (int i = 0; i < 32; i++) {
        int idx = i * NTHR + tid;                 // 0..8191 = ((l*64+kt)*32+ln)
        int ln = idx & 31, kt = (idx >> 5) & 63, l = idx >> 11;
        const float* W = ((kt < 32) ? Wih : Whh) + (size_t)l * 4 * Hd * Hd;
        int kb = (kt & 31) * 16 + (ln & 3) * 2;
        __half h8[8];
#pragma unroll
        for (int areg = 0; areg < 4; areg++) {
            int r = (ln >> 2) + (areg & 1) * 8;   // A row 0..15
            int grow = (r & 3) * Hd + u0 + (r >> 2);
            float2 v = *(const float2*)&W[(size_t)grow * Hd + kb + (areg >> 1) * 8];
            h8[areg * 2 + 0] = __float2half_rn(v.x);
            h8[areg * 2 + 1] = __float2half_rn(v.y);
        }
        *(uint4*)&sW[(size_t)idx * 8] = *(uint4*)h8;
    }

    // ---- prologue B: pack initial state (grid-strided) ----
    for (int i = cta * NTHR + tid; i < (NL + 1) * Hd * Bz; i += NCTA * NTHR) {
        int u = (i & 32767) >> 6, b = i & 63;
        if (i < Hd * Bz)
            g_Xin[0][0][xoff(u, b)] = __float2half_rn(y[b * Hd + u]);
        else {
            int l = (i >> 15) - 1;
            g_Hrec[0][l][xoff(u, b)] =
                __float2half_rn(h0[(size_t)l * Bz * Hd + b * Hd + u]);
        }
    }

    // epilogue mapping: thread -> (unit j, batch c)
    const int j = tid >> 6;
    const int c = tid & 63;
    const int u = u0 + j;
    const int xo = xoff(u, c);

    float cst[NL];
#pragma unroll
    for (int l = 0; l < NL; l++)
        cst[l] = c0[(size_t)l * Bz * Hd + c * Hd + u];

    float bias[NL][4];
#pragma unroll
    for (int l = 0; l < NL; l++)
#pragma unroll
        for (int g = 0; g < 4; g++)
            bias[l][g] = bih[l * 4 * Hd + g * Hd + u] + bhh[l * 4 * Hd + g * Hd + u];

    int T = Tmax;
    if (seqp) { int tv = *seqp; if (tv > 0 && tv <= Tmax) T = tv; }
    const int R = NL * T;

    // ---- prologue grid barrier ----
    __syncthreads();
    if (tid == 0) {
        arrive_release(&g_bar);
        wait_ge(&g_bar, NCTA);
    }
    __syncthreads();

    // warp roles
    const int kq  = w & 3;          // K quadrant (8 ktiles per half)
    const int nt0 = (w >> 2) * 4;   // first ntile of this warp's N half
    const int np0 = (w >> 2) * 2;   // first ntile-PAIR
    const int kt0 = kq * 8;         // plane-local first ktile
    const uint4* sA0 = (const uint4*)sW;

    uint4 bb[8][2];
    uint4 aX[8];
    float acc[4][4];
#pragma unroll
    for (int n = 0; n < 4; n++)
#pragma unroll
        for (int q = 0; q < 4; q++) acc[n][q] = 0.f;

    // Hrec half for round 0 (t=0, l=0, p=0)
    load_frags(bb, (const uint4*)&g_Hrec[0][0][0], kt0, np0, lane);
    mma_frags(acc, sA0 + (0 * 64 + 32 + kt0) * 32 + lane, bb);
    // preload Xin A-frags for round 0
    load_afrags(aX, sA0 + (0 * 64 + kt0) * 32 + lane);

    for (int r = 0; r < R; r++) {
        const int t = r >> 2, l = r & 3, p = t & 1;

        // wait(r-1): Xin plane for round r ready (prologue barrier covers r=0)
        if (r > 0) {
            if (tid == 0) wait_ge(&g_bar, (unsigned)(r + 1) * NCTA);
            __syncthreads();
        }

        // Xin half of round r (critical path; A-frags already in registers)
        load_frags(bb, (const uint4*)&g_Xin[p][l][0], kt0, np0, lane);
        mma_frags_reg(acc, aX, bb);

        // cross-warp K reduction (4-way) via smem
        {
            int gid = lane >> 2, tig = lane & 3;
#pragma unroll
            for (int n = 0; n < 4; n++) {
                int col = (nt0 + n) * 8 + tig * 2;
                *(float2*)&red[(kq * 16 + gid)     * RSTRIDE + col] =
                    make_float2(acc[n][0], acc[n][1]);
                *(float2*)&red[(kq * 16 + gid + 8) * RSTRIDE + col] =
                    make_float2(acc[n][2], acc[n][3]);
            }
        }
        __syncthreads();

        // early Hrec(r+1) fragment loads — latency hides under epilogue
        const int r2 = r + 1, l2 = r2 & 3, p2 = (r2 >> 2) & 1;
        if (r2 < R)
            load_frags(bb, (const uint4*)&g_Hrec[p2][l2][0], kt0, np0, lane);

        float s0 = 0.f, s1 = 0.f, s2 = 0.f, s3 = 0.f;
#pragma unroll
        for (int kk = 0; kk < 4; kk++) {
            const float* rw = &red[(kk * 16 + j * 4) * RSTRIDE + c];
            s0 += rw[0];
            s1 += rw[RSTRIDE];
            s2 += rw[2 * RSTRIDE];
            s3 += rw[3 * RSTRIDE];
        }

        float iG = sigm(s0 + bias[l][0]);
        float fG = sigm(s1 + bias[l][1]);
        float gG = tanhfast(s2 + bias[l][2]);
        float oG = sigm(s3 + bias[l][3]);
        float cn = fG * cst[l] + iG * gG;
        cst[l] = cn;
        float hn = oG * tanhfast(cn);

        // critical-path publish: ONLY the next-round Xin destination
        unsigned short hb = __half_as_ushort(__float2half_rn(hn));
        {
            __half* xdst = (l < NL - 1) ? &g_Xin[p][l + 1][0] : &g_Xin[p ^ 1][0][0];
            __stcg((unsigned short*)&xdst[xo], hb);
        }

        // arrive(r): syncthreads collects the Xin publishes; release-red orders
        // them before the counter increment.
        __syncthreads();           // also guards red reuse
        if (tid == 0) arrive_release(&g_bar);

        // ---- shadow region (off the critical path) ----
        // deferred publishes: Hrec plane (first read at round r+4, ordered by
        // our arrive(r+1)) and the output tensor (read only after kernel end).
        __stcg((unsigned short*)&g_Hrec[p ^ 1][l][xo], hb);
        if (l == NL - 1)
            out[((size_t)c * T + t) * Hd + u] = hn;   // out[b][t][u]

        // Hrec MMAs for round r+1 (fragments already in registers)
        if (r2 < R) {
#pragma unroll
            for (int n = 0; n < 4; n++)
#pragma unroll
                for (int q = 0; q < 4; q++) acc[n][q] = 0.f;
            mma_frags(acc, sA0 + (l2 * 64 + 32 + kt0) * 32 + lane, bb);
            // preload Xin A-frags for round r+1 (before the wait)
            load_afrags(aX, sA0 + (l2 * 64 + kt0) * 32 + lane);
        }
    }

    // self-reset barrier for next graph replay (deterministic state)
    if (cta == 0 && tid == 0) {
        wait_ge(&g_bar, (unsigned)(R + 1) * NCTA);
        *(volatile unsigned*)&g_bar = 0u;
    }
}

extern "C" void kernel_launch(void* const* d_in, const int* in_sizes, int n_in,
                              void* d_out, int out_size) {
    const float* y   = (const float*)d_in[0];
    const float* h0  = (const float*)d_in[1];
    const float* c0  = (const float*)d_in[2];
    const float* Wih = (const float*)d_in[3];
    const float* Whh = (const float*)d_in[4];
    const float* bih = (const float*)d_in[5];
    const float* bhh = (const float*)d_in[6];
    const int*   sl  = (n_in >= 8) ? (const int*)d_in[7] : nullptr;
    float* out = (float*)d_out;
    (void)in_sizes; (void)out_size;

    cudaFuncSetAttribute(lstm_all, cudaFuncAttributeMaxDynamicSharedMemorySize, SMEM_TOT);
    lstm_all<<<NCTA, NTHR, SMEM_TOT>>>(y, h0, c0, Wih, Whh, bih, bhh, sl, out);
}